// round 15
// baseline (speedup 1.0000x reference)
#include <cuda_runtime.h>
#include <math.h>

// Problem constants
#define B_ 8
#define S_ 512
#define D_ 512
#define H_ 8
#define DK_ 64
#define DV_ 64
#define DFF_ 2048
#define L_ 6
#define M_ (B_ * S_)               // 4096 rows
#define X_ELEMS (M_ * D_)          // 2,097,152
#define ATTN_PER_LAYER ((long)B_ * H_ * S_ * S_)  // 16,777,216
#define WLD (D_ * D_)              // 262144
#define WF (D_ * DFF_)             // 1048576

// Device scratch (allocations are forbidden; use __device__ globals)
__device__ float g_x[X_ELEMS];
__device__ float g_xr[X_ELEMS];    // tf32-rounded copy of x (GEMM A input)
__device__ float g_q[X_ELEMS];     // q; reused as split-K partial buffer later
__device__ float g_k[X_ELEMS];
__device__ float g_v[X_ELEMS];
__device__ float g_ctx[X_ELEMS];
__device__ float g_tmp[X_ELEMS];
__device__ float g_h1[M_ * DFF_];
__device__ float g_pos[S_ * D_];
__device__ float g_wr[6 * (4 * WLD + 2 * WF)];  // tf32-rounded weights

// ---------------------------------------------------------------------------
// helpers
// ---------------------------------------------------------------------------
__device__ __forceinline__ unsigned tfc(unsigned x) {
    unsigned r;
    asm("cvt.rna.tf32.f32 %0, %1;" : "=r"(r) : "f"(__uint_as_float(x)));
    return r;
}
__device__ __forceinline__ float frnd(float x) {
    return __uint_as_float(tfc(__float_as_uint(x)));
}

__device__ __forceinline__ void mma8(float* d, const unsigned* a, const unsigned* b) {
    asm volatile(
        "mma.sync.aligned.m16n8k8.row.col.f32.tf32.tf32.f32 "
        "{%0,%1,%2,%3}, {%4,%5,%6,%7}, {%8,%9}, {%0,%1,%2,%3};"
        : "+f"(d[0]), "+f"(d[1]), "+f"(d[2]), "+f"(d[3])
        : "r"(a[0]), "r"(a[1]), "r"(a[2]), "r"(a[3]), "r"(b[0]), "r"(b[1]));
}

__device__ __forceinline__ void ldsm_x4(unsigned* r, unsigned addr) {
    asm volatile("ldmatrix.sync.aligned.m8n8.x4.shared.b16 {%0,%1,%2,%3}, [%4];"
                 : "=r"(r[0]), "=r"(r[1]), "=r"(r[2]), "=r"(r[3]) : "r"(addr));
}

__device__ __forceinline__ void cpa16(unsigned dst, const void* src) {
    asm volatile("cp.async.cg.shared.global [%0], [%1], 16;" :: "r"(dst), "l"(src));
}
__device__ __forceinline__ void cpa_commit() {
    asm volatile("cp.async.commit_group;" ::: "memory");
}
template <int N>
__device__ __forceinline__ void cpa_wait() {
    asm volatile("cp.async.wait_group %0;" :: "n"(N) : "memory");
}

// ---------------------------------------------------------------------------
// tf32 rounding copy (for weights)
// ---------------------------------------------------------------------------
__global__ void round_kernel(const float4* __restrict__ in,
                             float4* __restrict__ out, int n4) {
    int i = blockIdx.x * blockDim.x + threadIdx.x;
    if (i >= n4) return;
    float4 v = in[i];
    v.x = frnd(v.x); v.y = frnd(v.y); v.z = frnd(v.z); v.w = frnd(v.w);
    out[i] = v;
}

// ---------------------------------------------------------------------------
// Positional table (double precision to match numpy float64 path)
// ---------------------------------------------------------------------------
__global__ void pos_kernel(float* __restrict__ pos) {
    int idx = blockIdx.x * blockDim.x + threadIdx.x;
    if (idx >= S_ * D_) return;
    int s = idx >> 9;
    int d = idx & 511;
    double val = 0.0;
    if (s > 0) {
        double ang = (double)s * exp(-log(10000.0) * (2.0 * (double)d / (double)D_));
        val = (d & 1) ? cos(ang) : sin(ang);
    }
    pos[idx] = (float)val;
}

__global__ void add_pos_kernel(float* __restrict__ x, float* __restrict__ xr,
                               const float* __restrict__ enc,
                               const float* __restrict__ pos) {
    int idx = blockIdx.x * blockDim.x + threadIdx.x;
    if (idx >= X_ELEMS) return;
    int sd = idx & (S_ * D_ - 1);
    float v = enc[idx] + pos[sd];
    x[idx] = v;
    xr[idx] = frnd(v);
}

// ---------------------------------------------------------------------------
// mma.sync tf32 GEMM, BK=32 cp.async pipeline, 3 stages, 128 threads,
// 2x2 warp grid, 64x64 warp tiles (R13 best configuration).
//   C[m,n] = alpha * sum_k A[m,k] * (TB ? B[n,k] : B[k,n])  (+ epilogue)
// CVTA: cvt.rna A frags post-ldmatrix. ROUT: round outputs to tf32.
// epi: 0 none, 1 relu, 2 += R.
// ---------------------------------------------------------------------------
#define NTH 128

template <int BM, int BN, bool TB, int STAGES, int BK>
struct GCfg {
    static constexpr int ASTR = BK + 4;
    static constexpr int ABUF = BM * ASTR;
    static constexpr int BSTR = TB ? (BK + 4) : (BN + 8);
    static constexpr int BBUF = TB ? (BN * (BK + 4)) : (BK * (BN + 8));
    static constexpr int SMEM_BYTES = STAGES * (ABUF + BBUF) * 4;
};

template <int BM, int BN, bool TB, int STAGES, int BK, bool CVTA, bool ROUT>
__device__ __forceinline__ void gemm_body(
    float* __restrict__ smem,
    const float* __restrict__ A, int lda,
    const float* __restrict__ Bg, int ldb,
    float* __restrict__ C, int ldc,
    const float* __restrict__ R,
    int K, float alpha, int epi) {
    using CF = GCfg<BM, BN, TB, STAGES, BK>;
    constexpr int ASTR = CF::ASTR, ABUF = CF::ABUF;
    constexpr int BSTR = CF::BSTR, BBUF = CF::BBUF;
    constexpr int KF4 = BK / 4;
    constexpr int RA = NTH / KF4;
    constexpr int AF = BM / RA;
    constexpr int KF4N = BN / 4;
    constexpr int RB = TB ? (NTH / KF4) : (NTH / KF4N);
    constexpr int BF = TB ? (BN / RB) : (BK / RB);
    constexpr int WM = BM / 2, WN = BN / 2;
    constexpr int MT = WM / 16, NT = WN / 8;
    constexpr int NKS = BK / 8;

    const int tid = threadIdx.x;
    const int lane = tid & 31;
    const int warp = tid >> 5;
    const int g = lane >> 2;
    const int tg = lane & 3;
    const int wr = warp & 1;
    const int wc = warp >> 1;
    const int m0 = blockIdx.y * BM;
    const int n0 = blockIdx.x * BN;

    float* As = smem;
    float* Bs = smem + STAGES * ABUF;
    const unsigned as_u = (unsigned)__cvta_generic_to_shared(As);
    const unsigned bs_u = (unsigned)__cvta_generic_to_shared(Bs);

    const int ra = tid / KF4, ca = tid % KF4;
    const float* pA = A + (long)(m0 + ra) * lda + ca * 4;
    const unsigned aoff0 = as_u + (unsigned)(ra * ASTR + ca * 4) * 4u;

    const float* pB;
    unsigned boff0;
    if (TB) {
        const int rb = tid / KF4, cb = tid % KF4;
        pB = Bg + (long)(n0 + rb) * ldb + cb * 4;
        boff0 = bs_u + (unsigned)(rb * BSTR + cb * 4) * 4u;
    } else {
        const int rb = tid / KF4N, cb = tid % KF4N;
        pB = Bg + (long)rb * ldb + n0 + cb * 4;
        boff0 = bs_u + (unsigned)(rb * BSTR + cb * 4) * 4u;
    }
    const long stepB = TB ? BK : (long)BK * ldb;

    int slot_ld = 0;
    auto load_stage = [&]() {
        const unsigned ao = (unsigned)(slot_ld * ABUF) * 4u;
        const unsigned bo = (unsigned)(slot_ld * BBUF) * 4u;
#pragma unroll
        for (int it = 0; it < AF; it++)
            cpa16(aoff0 + ao + (unsigned)(it * RA * ASTR * 4),
                  pA + (long)it * RA * lda);
        pA += BK;
#pragma unroll
        for (int it = 0; it < BF; it++)
            cpa16(boff0 + bo + (unsigned)(it * RB * BSTR * 4),
                  pB + (long)it * RB * ldb);
        pB += stepB;
        slot_ld = (slot_ld + 1 == STAGES) ? 0 : slot_ld + 1;
    };

    const unsigned a_base =
        as_u + (unsigned)(((wr * WM + (lane & 7) + 8 * ((lane >> 3) & 1)) * ASTR +
                           4 * (lane >> 4)) << 2);
    unsigned b_base = 0;
    if (TB) {
        b_base = bs_u + (unsigned)(((wc * WN + (lane & 7) + 8 * (lane >> 4)) * BSTR +
                                    4 * ((lane >> 3) & 1)) << 2);
    }

    float acc[MT][NT][4];
#pragma unroll
    for (int i = 0; i < MT; i++)
#pragma unroll
        for (int j = 0; j < NT; j++)
#pragma unroll
            for (int e = 0; e < 4; e++) acc[i][j][e] = 0.0f;

    const int nch = K / BK;
#pragma unroll
    for (int s = 0; s < STAGES - 1; s++) {
        if (s < nch) load_stage();
        cpa_commit();
    }

    int slot_cmp = 0;
    for (int c = 0; c < nch; c++) {
        cpa_wait<STAGES - 2>();
        __syncthreads();
        const unsigned abp = a_base + (unsigned)(slot_cmp * ABUF) * 4u;
        const unsigned bbp = b_base + (unsigned)(slot_cmp * BBUF) * 4u;
        const float* bbf = Bs + slot_cmp * BBUF;
        slot_cmp = (slot_cmp + 1 == STAGES) ? 0 : slot_cmp + 1;

#pragma unroll
        for (int ks = 0; ks < NKS; ks++) {
            unsigned afr[MT][4], bfr[NT][2];
#pragma unroll
            for (int i = 0; i < MT; i++) {
                ldsm_x4(afr[i], abp + i * (16 * ASTR * 4) + ks * 32);
                if (CVTA) {
#pragma unroll
                    for (int e = 0; e < 4; e++) afr[i][e] = tfc(afr[i][e]);
                }
            }
            if (TB) {
#pragma unroll
                for (int j = 0; j < NT; j += 2)
                    ldsm_x4(&bfr[j][0], bbp + j * (8 * BSTR * 4) + ks * 32);
            } else {
#pragma unroll
                for (int j = 0; j < NT; j++) {
                    int n = wc * WN + j * 8 + g;
                    bfr[j][0] = __float_as_uint(bbf[(ks * 8 + tg) * BSTR + n]);
                    bfr[j][1] = __float_as_uint(bbf[(ks * 8 + 4 + tg) * BSTR + n]);
                }
            }
#pragma unroll
            for (int i = 0; i < MT; i++)
#pragma unroll
                for (int j = 0; j < NT; j++) mma8(acc[i][j], afr[i], bfr[j]);
        }

        if (c + STAGES - 1 < nch) load_stage();
        cpa_commit();
    }

    // Epilogue
#pragma unroll
    for (int i = 0; i < MT; i++) {
        int r0 = m0 + wr * WM + i * 16 + g;
#pragma unroll
        for (int j = 0; j < NT; j++) {
            int col = n0 + wc * WN + j * 8 + tg * 2;
            float v0 = acc[i][j][0] * alpha;
            float v1 = acc[i][j][1] * alpha;
            float v2 = acc[i][j][2] * alpha;
            float v3 = acc[i][j][3] * alpha;
            if (epi == 1) {
                v0 = fmaxf(v0, 0.0f); v1 = fmaxf(v1, 0.0f);
                v2 = fmaxf(v2, 0.0f); v3 = fmaxf(v3, 0.0f);
            } else if (epi == 2) {
                v0 += R[(long)r0 * ldc + col];
                v1 += R[(long)r0 * ldc + col + 1];
                v2 += R[(long)(r0 + 8) * ldc + col];
                v3 += R[(long)(r0 + 8) * ldc + col + 1];
            }
            if (ROUT) {
                v0 = frnd(v0); v1 = frnd(v1); v2 = frnd(v2); v3 = frnd(v3);
            }
            float2 p01; p01.x = v0; p01.y = v1;
            float2 p23; p23.x = v2; p23.y = v3;
            *reinterpret_cast<float2*>(&C[(long)r0 * ldc + col]) = p01;
            *reinterpret_cast<float2*>(&C[(long)(r0 + 8) * ldc + col]) = p23;
        }
    }
}

template <int BM, int BN, bool TB, int STAGES, int BK, bool CVTA, bool ROUT>
__global__ void __launch_bounds__(NTH, 2)
gemm_cp(const float* __restrict__ A, int lda, long sAb, long sAh,
        const float* __restrict__ Bg, int ldb, long sBb, long sBh,
        float* __restrict__ C, int ldc, long sCb, long sCh,
        const float* __restrict__ R,
        int K, float alpha, int epi, int hdiv) {
    extern __shared__ float smem[];
    const int z = blockIdx.z;
    const int zb = z / hdiv;
    const int zh = z % hdiv;
    gemm_body<BM, BN, TB, STAGES, BK, CVTA, ROUT>(
        smem,
        A + (long)zb * sAb + (long)zh * sAh, lda,
        Bg + (long)zb * sBb + (long)zh * sBh, ldb,
        C + (long)zb * sCb + (long)zh * sCh, ldc,
        R, K, alpha, epi);
}

// Fused Q/K/V projection: blockIdx.z selects the weight/output pair.
__global__ void __launch_bounds__(NTH, 2)
qkv_cp(const float* __restrict__ x,
       const float* __restrict__ Wq, const float* __restrict__ Wk,
       const float* __restrict__ Wv,
       float* __restrict__ q, float* __restrict__ k, float* __restrict__ v) {
    extern __shared__ float smem[];
    const int z = blockIdx.z;
    const float* W = (z == 0) ? Wq : (z == 1) ? Wk : Wv;
    float* C = (z == 0) ? q : (z == 1) ? k : v;
    gemm_body<128, 128, false, 3, 32, false, true>(smem, x, D_, W, D_, C, D_,
                                                   nullptr, D_, 1.0f, 0);
}

// ---------------------------------------------------------------------------
// Fused scores + mask + softmax (phases A+B of the R7-verified fused kernel).
// One CTA per (qtile64, b*h); 256 threads; writes normalized probs to attn.
// smem: Ks[512*68] (reused as P[64][516]) | Qs[64*68] | madd[512]
// ---------------------------------------------------------------------------
#define KS_STR 68
#define P_STR 516
#define AT_QS 34816                 // 512*68 floats
#define AT_MADD (AT_QS + 4352)      // + 64*68
#define AT_SMEM ((AT_MADD + 512) * 4)  // 158720 bytes

__global__ void __launch_bounds__(256, 1)
attn_ss(const float* __restrict__ q, const float* __restrict__ k,
        const int* __restrict__ mask, float* __restrict__ attn) {
    extern __shared__ float sm[];
    float* Ks = sm;
    float* Qs = sm + AT_QS;
    float* madd = sm + AT_MADD;
    float* P = sm;  // reuses K region after phase A

    const int tid = threadIdx.x;
    const int lane = tid & 31;
    const int warp = tid >> 5;
    const int g = lane >> 2;
    const int tg = lane & 3;
    const int bh = blockIdx.y;
    const int b = bh >> 3;
    const int h = bh & 7;
    const int q0 = blockIdx.x * 64;

    const unsigned ks_u = (unsigned)__cvta_generic_to_shared(Ks);
    const unsigned qs_u = (unsigned)__cvta_generic_to_shared(Qs);

    // mask -> additive bias
    {
        const int* mrow = mask + b * S_;
        madd[tid] = (mrow[tid] == 0) ? -1e9f : 0.0f;
        madd[tid + 256] = (mrow[tid + 256] == 0) ? -1e9f : 0.0f;
    }
    // Q tile (64x64) and full K panel (512x64), stride-68 smem
    {
        const float* qg = q + ((long)(b * S_ + q0)) * D_ + h * 64;
#pragma unroll
        for (int it = 0; it < 4; it++) {
            int f = tid + it * 256;
            int row = f >> 4, c4 = f & 15;
            cpa16(qs_u + (unsigned)(row * KS_STR + c4 * 4) * 4u,
                  qg + (long)row * D_ + c4 * 4);
        }
        const float* kg = k + ((long)(b * S_)) * D_ + h * 64;
#pragma unroll
        for (int it = 0; it < 32; it++) {
            int f = tid + it * 256;
            int row = f >> 4, c4 = f & 15;
            cpa16(ks_u + (unsigned)(row * KS_STR + c4 * 4) * 4u,
                  kg + (long)row * D_ + c4 * 4);
        }
    }
    cpa_commit();
    cpa_wait<0>();
    __syncthreads();

    // ---- Phase A: scores. Warp w covers keys [64w, 64w+64), all 64 queries.
    float acc[4][8][4];
#pragma unroll
    for (int i = 0; i < 4; i++)
#pragma unroll
        for (int j = 0; j < 8; j++)
#pragma unroll
            for (int e = 0; e < 4; e++) acc[i][j][e] = 0.0f;

    const unsigned a_base =
        qs_u + (unsigned)((((lane & 7) + 8 * ((lane >> 3) & 1)) * KS_STR +
                           4 * (lane >> 4)) << 2);
    const unsigned b_base =
        ks_u + (unsigned)(((warp * 64 + (lane & 7) + 8 * (lane >> 4)) * KS_STR +
                           4 * ((lane >> 3) & 1)) << 2);
#pragma unroll
    for (int ks = 0; ks < 8; ks++) {
        unsigned af[4][4], bf[8][2];
#pragma unroll
        for (int i = 0; i < 4; i++)
            ldsm_x4(af[i], a_base + i * (16 * KS_STR * 4) + ks * 32);
#pragma unroll
        for (int j = 0; j < 8; j += 2)
            ldsm_x4(&bf[j][0], b_base + j * (8 * KS_STR * 4) + ks * 32);
#pragma unroll
        for (int i = 0; i < 4; i++)
#pragma unroll
            for (int j = 0; j < 8; j++) mma8(acc[i][j], af[i], bf[j]);
    }
    __syncthreads();  // everyone done reading Ks

    // Park raw scores into P (overwrites Ks)
#pragma unroll
    for (int i = 0; i < 4; i++) {
        int r0 = 16 * i + g;
#pragma unroll
        for (int j = 0; j < 8; j++) {
            int c = warp * 64 + 8 * j + tg * 2;
            float2 lo; lo.x = acc[i][j][0]; lo.y = acc[i][j][1];
            float2 hi; hi.x = acc[i][j][2]; hi.y = acc[i][j][3];
            *reinterpret_cast<float2*>(&P[r0 * P_STR + c]) = lo;
            *reinterpret_cast<float2*>(&P[(r0 + 8) * P_STR + c]) = hi;
        }
    }
    __syncthreads();

    // ---- Phase B: softmax, warp per row (8 rows/warp); write probs to gmem.
#pragma unroll
    for (int rr = 0; rr < 8; rr++) {
        const int r = warp * 8 + rr;
        float* pr = P + r * P_STR;
        float4 vv[4];
        float mx = -3.4e38f;
#pragma unroll
        for (int c4 = 0; c4 < 4; c4++) {
            int col = c4 * 128 + lane * 4;
            float4 t = *reinterpret_cast<float4*>(&pr[col]);
            t.x = fmaf(t.x, 0.125f, madd[col]);
            t.y = fmaf(t.y, 0.125f, madd[col + 1]);
            t.z = fmaf(t.z, 0.125f, madd[col + 2]);
            t.w = fmaf(t.w, 0.125f, madd[col + 3]);
            vv[c4] = t;
            mx = fmaxf(mx, fmaxf(fmaxf(t.x, t.y), fmaxf(t.z, t.w)));
        }
#pragma unroll
        for (int o = 16; o; o >>= 1) mx = fmaxf(mx, __shfl_xor_sync(~0u, mx, o));
        float sum = 0.0f;
#pragma unroll
        for (int c4 = 0; c4 < 4; c4++) {
            vv[c4].x = __expf(vv[c4].x - mx);
            vv[c4].y = __expf(vv[c4].y - mx);
            vv[c4].z = __expf(vv[c4].z - mx);
            vv[c4].w = __expf(vv[c4].w - mx);
            sum += vv[c4].x + vv[c4].y + vv[c4].z + vv[c4].w;
        }
#pragma unroll
        for (int o = 16; o; o >>= 1) sum += __shfl_xor_sync(~0u, sum, o);
        const float inv = 1.0f / sum;
        float* ag = attn + ((long)bh * S_ + q0 + r) * S_;
#pragma unroll
        for (int c4 = 0; c4 < 4; c4++) {
            int col = c4 * 128 + lane * 4;
            float4 t = vv[c4];
            t.x *= inv; t.y *= inv; t.z *= inv; t.w *= inv;
            *reinterpret_cast<float4*>(&ag[col]) = t;
        }
    }
}

// ---------------------------------------------------------------------------
// LayerNorm: in = p0 + p1 + residual (split-K reduce fused); dual output.
// ---------------------------------------------------------------------------
__global__ void ln3_kernel(const float* __restrict__ p0,
                           const float* __restrict__ p1,
                           const float* __restrict__ res,
                           const float* __restrict__ g,
                           const float* __restrict__ bb,
                           float* __restrict__ out,
                           float* __restrict__ outr) {
    const int row = blockIdx.x;
    const long base = (long)row * D_;
    const int t = threadIdx.x;

    float x0 = (p0[base + t] + p1[base + t]) + res[base + t];
    float x1 = (p0[base + t + 256] + p1[base + t + 256]) + res[base + t + 256];

    __shared__ float red[256];
    red[t] = x0 + x1;
    __syncthreads();
#pragma unroll
    for (int s = 128; s > 0; s >>= 1) {
        if (t < s) red[t] += red[t + s];
        __syncthreads();
    }
    const float mean = red[0] * (1.0f / D_);
    __syncthreads();

    float d0 = x0 - mean;
    float d1 = x1 - mean;
    red[t] = d0 * d0 + d1 * d1;
    __syncthreads();
#pragma unroll
    for (int s = 128; s > 0; s >>= 1) {
        if (t < s) red[t] += red[t + s];
        __syncthreads();
    }
    const float var = red[0] * (1.0f / D_);
    const float rs = rsqrtf(var + 1e-5f);

    float o0 = d0 * rs * g[t] + bb[t];
    float o1 = d1 * rs * g[t + 256] + bb[t + 256];
    out[base + t] = o0;
    out[base + t + 256] = o1;
    outr[base + t] = frnd(o0);
    outr[base + t + 256] = frnd(o1);
}

// ---------------------------------------------------------------------------
extern "C" void kernel_launch(void* const* d_in, const int* in_sizes, int n_in,
                              void* d_out, int out_size) {
    const float* enc = (const float*)d_in[0];
    const int* mask = (const int*)d_in[1];
    const float* Wq = (const float*)d_in[2];
    const float* Wk = (const float*)d_in[3];
    const float* Wv = (const float*)d_in[4];
    const float* Wo = (const float*)d_in[5];
    const float* ln1g = (const float*)d_in[6];
    const float* ln1b = (const float*)d_in[7];
    const float* W1 = (const float*)d_in[8];
    const float* W2 = (const float*)d_in[9];
    const float* ln2g = (const float*)d_in[10];
    const float* ln2b = (const float*)d_in[11];

    float *x, *xr, *q, *k, *v, *ctx, *tmp, *h1, *pos, *wr;
    cudaGetSymbolAddress((void**)&x, g_x);
    cudaGetSymbolAddress((void**)&xr, g_xr);
    cudaGetSymbolAddress((void**)&q, g_q);
    cudaGetSymbolAddress((void**)&k, g_k);
    cudaGetSymbolAddress((void**)&v, g_v);
    cudaGetSymbolAddress((void**)&ctx, g_ctx);
    cudaGetSymbolAddress((void**)&tmp, g_tmp);
    cudaGetSymbolAddress((void**)&h1, g_h1);
    cudaGetSymbolAddress((void**)&pos, g_pos);
    cudaGetSymbolAddress((void**)&wr, g_wr);

    float* Wq_r = wr;
    float* Wk_r = Wq_r + 6 * WLD;
    float* Wv_r = Wk_r + 6 * WLD;
    float* Wo_r = Wv_r + 6 * WLD;
    float* W1_r = Wo_r + 6 * WLD;
    float* W2_r = W1_r + 6 * WF;

    float* out_x = (float*)d_out;
    float* out_attn = out_x + X_ELEMS;

    constexpr int SM_PROJ = GCfg<128, 128, false, 3, 32>::SMEM_BYTES;  // 107520
    constexpr int SM_CTX  = GCfg<128, 64, false, 3, 32>::SMEM_BYTES;   // 82944
    cudaFuncSetAttribute(gemm_cp<128, 128, false, 3, 32, false, false>,
                         cudaFuncAttributeMaxDynamicSharedMemorySize, SM_PROJ);
    cudaFuncSetAttribute(gemm_cp<128, 128, false, 3, 32, false, true>,
                         cudaFuncAttributeMaxDynamicSharedMemorySize, SM_PROJ);
    cudaFuncSetAttribute(gemm_cp<128, 64, false, 3, 32, true, true>,
                         cudaFuncAttributeMaxDynamicSharedMemorySize, SM_CTX);
    cudaFuncSetAttribute(qkv_cp,
                         cudaFuncAttributeMaxDynamicSharedMemorySize, SM_PROJ);
    cudaFuncSetAttribute(attn_ss,
                         cudaFuncAttributeMaxDynamicSharedMemorySize, AT_SMEM);

    // Round all weights to tf32 once per launch
    round_kernel<<<(6 * WLD / 4 + 255) / 256, 256>>>(
        (const float4*)Wq, (float4*)Wq_r, 6 * WLD / 4);
    round_kernel<<<(6 * WLD / 4 + 255) / 256, 256>>>(
        (const float4*)Wk, (float4*)Wk_r, 6 * WLD / 4);
    round_kernel<<<(6 * WLD / 4 + 255) / 256, 256>>>(
        (const float4*)Wv, (float4*)Wv_r, 6 * WLD / 4);
    round_kernel<<<(6 * WLD / 4 + 255) / 256, 256>>>(
        (const float4*)Wo, (float4*)Wo_r, 6 * WLD / 4);
    round_kernel<<<(6 * WF / 4 + 255) / 256, 256>>>(
        (const float4*)W1, (float4*)W1_r, 6 * WF / 4);
    round_kernel<<<(6 * WF / 4 + 255) / 256, 256>>>(
        (const float4*)W2, (float4*)W2_r, 6 * WF / 4);

    pos_kernel<<<(S_ * D_ + 255) / 256, 256>>>(pos);
    add_pos_kernel<<<(X_ELEMS + 255) / 256, 256>>>(x, xr, enc, pos);

    const long CSPLIT = q - tmp;   // split-K: z=0 -> tmp, z=1 -> q

    for (int l = 0; l < L_; l++) {
        float* attn_l = out_attn + (long)l * ATTN_PER_LAYER;

        // Fused Q,K,V projections (rounded outputs)
        qkv_cp<<<dim3(4, 32, 3), NTH, SM_PROJ>>>(
            xr, Wq_r + l * WLD, Wk_r + l * WLD, Wv_r + l * WLD, q, k, v);

        // Fused scores + mask + softmax -> attn probs (exact fp32 out)
        attn_ss<<<dim3(8, 64), 256, AT_SMEM>>>(q, k, mask, attn_l);

        // ctx: per (b,h): attn[512,512] @ V[512,64] (A needs cvt; rounded out)
        gemm_cp<128, 64, false, 3, 32, true, true>
            <<<dim3(1, 4, B_ * H_), NTH, SM_CTX>>>(
            attn_l, S_, (long)H_ * S_ * S_, (long)S_ * S_,
            v, D_, (long)S_ * D_, DV_,
            ctx, D_, (long)S_ * D_, DV_,
            nullptr, S_, 1.0f, 0, H_);

        // Wo projection, split-K=2 -> partials tmp/q; reduce fused into LN1
        gemm_cp<128, 128, false, 3, 32, false, false>
            <<<dim3(4, 32, 2), NTH, SM_PROJ>>>(
            ctx, D_, 0, 256,
            Wo_r + l * WLD, D_, 0, (long)256 * D_,
            tmp, D_, 0, CSPLIT,
            nullptr, 256, 1.0f, 0, 2);
        ln3_kernel<<<M_, 256>>>(tmp, q, x, ln1g + l * D_, ln1b + l * D_, x, xr);

        // FFN: relu(xr @ W1) (rounded) -> h1
        gemm_cp<128, 128, false, 3, 32, false, true>
            <<<dim3(16, 32, 1), NTH, SM_PROJ>>>(
            xr, D_, 0, 0, W1_r + l * WF, DFF_, 0, 0, h1, DFF_, 0, 0, nullptr, D_,
            1.0f, 1, 1);
        // W2, split-K=2 -> partials tmp/q; reduce fused into LN2
        gemm_cp<128, 128, false, 3, 32, false, false>
            <<<dim3(4, 32, 2), NTH, SM_PROJ>>>(
            h1, DFF_, 0, 1024,
            W2_r + l * WF, D_, 0, (long)1024 * D_,
            tmp, D_, 0, CSPLIT,
            nullptr, 1024, 1.0f, 0, 2);
        ln3_kernel<<<M_, 256>>>(tmp, q, x, ln2g + l * D_, ln2b + l * D_, x, xr);
    }

    cudaMemcpyAsync(out_x, x, (size_t)X_ELEMS * sizeof(float),
                    cudaMemcpyDeviceToDevice, 0);
}

// round 16
// speedup vs baseline: 1.4195x; 1.4195x over previous
#include <cuda_runtime.h>
#include <cuda_fp16.h>
#include <math.h>

// Problem constants
#define B_ 8
#define S_ 512
#define D_ 512
#define H_ 8
#define DK_ 64
#define DV_ 64
#define DFF_ 2048
#define L_ 6
#define M_ (B_ * S_)               // 4096 rows
#define X_ELEMS (M_ * D_)          // 2,097,152
#define ATTN_PER_LAYER ((long)B_ * H_ * S_ * S_)  // 16,777,216
#define WLD (D_ * D_)              // 262144
#define WF (D_ * DFF_)             // 1048576

// Device scratch (allocations forbidden; __device__ globals)
__device__ float  g_x[X_ELEMS];          // residual stream (fp32)
__device__ float  g_tmp[X_ELEMS];        // split-K partial 0 (fp32)
__device__ float  g_p2[X_ELEMS];         // split-K partial 1 (fp32)
__device__ float  g_pos[S_ * D_];
__device__ __half g_xh[X_ELEMS];         // fp16 copy of x (GEMM A input)
__device__ __half g_qh[X_ELEMS];
__device__ __half g_kh[X_ELEMS];
__device__ __half g_vh[X_ELEMS];
__device__ __half g_ch[X_ELEMS];         // ctx fp16
__device__ __half g_h1h[M_ * DFF_];      // FFN hidden fp16
__device__ __half g_ph[ATTN_PER_LAYER];  // attn probs fp16 (for P@V)
__device__ __half g_wh[6 * (4 * WLD + 2 * WF)];  // fp16 weights

// ---------------------------------------------------------------------------
// helpers
// ---------------------------------------------------------------------------
__device__ __forceinline__ void mma16(float* d, const unsigned* a, const unsigned* b) {
    asm volatile(
        "mma.sync.aligned.m16n8k16.row.col.f32.f16.f16.f32 "
        "{%0,%1,%2,%3}, {%4,%5,%6,%7}, {%8,%9}, {%0,%1,%2,%3};"
        : "+f"(d[0]), "+f"(d[1]), "+f"(d[2]), "+f"(d[3])
        : "r"(a[0]), "r"(a[1]), "r"(a[2]), "r"(a[3]), "r"(b[0]), "r"(b[1]));
}
__device__ __forceinline__ void ldsm_x4(unsigned* r, unsigned addr) {
    asm volatile("ldmatrix.sync.aligned.m8n8.x4.shared.b16 {%0,%1,%2,%3}, [%4];"
                 : "=r"(r[0]), "=r"(r[1]), "=r"(r[2]), "=r"(r[3]) : "r"(addr));
}
__device__ __forceinline__ void ldsm_x4t(unsigned* r, unsigned addr) {
    asm volatile("ldmatrix.sync.aligned.m8n8.x4.trans.shared.b16 {%0,%1,%2,%3}, [%4];"
                 : "=r"(r[0]), "=r"(r[1]), "=r"(r[2]), "=r"(r[3]) : "r"(addr));
}
__device__ __forceinline__ void cpa16(unsigned dst, const void* src) {
    asm volatile("cp.async.cg.shared.global [%0], [%1], 16;" :: "r"(dst), "l"(src));
}
__device__ __forceinline__ void cpa_commit() {
    asm volatile("cp.async.commit_group;" ::: "memory");
}
template <int N>
__device__ __forceinline__ void cpa_wait() {
    asm volatile("cp.async.wait_group %0;" :: "n"(N) : "memory");
}

// ---------------------------------------------------------------------------
// fp32 -> fp16 rounding copy (weights)
// ---------------------------------------------------------------------------
__global__ void round_h(const float4* __restrict__ in,
                        __half2* __restrict__ out, int n4) {
    int i = blockIdx.x * blockDim.x + threadIdx.x;
    if (i >= n4) return;
    float4 v = in[i];
    out[2 * i] = __floats2half2_rn(v.x, v.y);
    out[2 * i + 1] = __floats2half2_rn(v.z, v.w);
}

// ---------------------------------------------------------------------------
// Positional table (double precision, matches numpy float64 path)
// ---------------------------------------------------------------------------
__global__ void pos_kernel(float* __restrict__ pos) {
    int idx = blockIdx.x * blockDim.x + threadIdx.x;
    if (idx >= S_ * D_) return;
    int s = idx >> 9;
    int d = idx & 511;
    double val = 0.0;
    if (s > 0) {
        double ang = (double)s * exp(-log(10000.0) * (2.0 * (double)d / (double)D_));
        val = (d & 1) ? cos(ang) : sin(ang);
    }
    pos[idx] = (float)val;
}

__global__ void add_pos_kernel(float* __restrict__ x, __half* __restrict__ xh,
                               const float* __restrict__ enc,
                               const float* __restrict__ pos) {
    int idx = blockIdx.x * blockDim.x + threadIdx.x;
    if (idx >= X_ELEMS) return;
    int sd = idx & (S_ * D_ - 1);
    float v = enc[idx] + pos[sd];
    x[idx] = v;
    xh[idx] = __float2half_rn(v);
}

// ---------------------------------------------------------------------------
// fp16 tensor-core GEMM (m16n8k16), BK=32 cp.async pipeline, 3 stages,
// 128 threads, 2x2 warp grid, 64x(BN/2) warp tiles.
//   C[m,n] = sum_k A[m,k] * B[k,n]   (A fp16 [m][k]; B fp16 k-major [k][n])
// A frags: ldmatrix.x4; B frags: ldmatrix.x4.trans. fp32 accumulation.
// RELU: relu epilogue. OUTH: fp16 output (else fp32, for split-K partials).
// ---------------------------------------------------------------------------
#define NTH 128

template <int BM, int BN, int STG, int BK>
struct HCfg {
    static constexpr int ASTR = BK + 8;             // halves
    static constexpr int ABUF = BM * ASTR;
    static constexpr int BSTR = BN + 8;
    static constexpr int BBUF = BK * BSTR;
    static constexpr int SMEM_BYTES = STG * (ABUF + BBUF) * 2;
};

template <int BM, int BN, int STG, int BK, bool RELU, bool OUTH>
__device__ __forceinline__ void hgemm_body(
    const __half* __restrict__ A, int lda,
    const __half* __restrict__ Bg, int ldb,
    void* __restrict__ Cv, int ldc, int K) {
    using CF = HCfg<BM, BN, STG, BK>;
    constexpr int ASTR = CF::ASTR, ABUF = CF::ABUF;
    constexpr int BSTR = CF::BSTR, BBUF = CF::BBUF;
    constexpr int AF = (BM * BK) / (8 * NTH);
    constexpr int BF = (BK * BN) / (8 * NTH);
    constexpr int BROW = NTH / (BN / 8);
    constexpr int WM = BM / 2, WN = BN / 2;
    constexpr int MT = WM / 16, NT = WN / 8;

    extern __shared__ __half hs[];
    __half* As = hs;
    __half* Bs = hs + STG * ABUF;
    const unsigned as_u = (unsigned)__cvta_generic_to_shared(As);
    const unsigned bs_u = (unsigned)__cvta_generic_to_shared(Bs);

    const int tid = threadIdx.x;
    const int lane = tid & 31;
    const int warp = tid >> 5;
    const int g = lane >> 2;
    const int tg = lane & 3;
    const int wr = warp & 1;
    const int wc = warp >> 1;
    const int m0 = blockIdx.y * BM;
    const int n0 = blockIdx.x * BN;

    const int ra = tid >> 2, ca = tid & 3;
    const __half* pA = A + (long)(m0 + ra) * lda + ca * 8;
    const unsigned aoff0 = as_u + (unsigned)(ra * ASTR + ca * 8) * 2u;
    const int rb = tid / (BN / 8), cb = tid % (BN / 8);
    const __half* pB = Bg + (long)rb * ldb + n0 + cb * 8;
    const unsigned boff0 = bs_u + (unsigned)(rb * BSTR + cb * 8) * 2u;

    int slot_ld = 0;
    auto load_stage = [&]() {
        const unsigned ao = (unsigned)(slot_ld * ABUF) * 2u;
        const unsigned bo = (unsigned)(slot_ld * BBUF) * 2u;
#pragma unroll
        for (int it = 0; it < AF; it++)
            cpa16(aoff0 + ao + (unsigned)(it * (NTH / 4) * ASTR) * 2u,
                  pA + (long)it * (NTH / 4) * lda);
        pA += BK;
#pragma unroll
        for (int it = 0; it < BF; it++)
            cpa16(boff0 + bo + (unsigned)(it * BROW * BSTR) * 2u,
                  pB + (long)it * BROW * ldb);
        pB += (long)BK * ldb;
        slot_ld = (slot_ld + 1 == STG) ? 0 : slot_ld + 1;
    };

    const unsigned a_base =
        as_u + (unsigned)(((wr * WM + (lane & 7) + 8 * ((lane >> 3) & 1)) * ASTR +
                           (lane >> 4) * 8) * 2);
    const unsigned b_base =
        bs_u + (unsigned)((((lane & 7) + 8 * ((lane >> 3) & 1)) * BSTR +
                           wc * WN + (lane >> 4) * 8) * 2);

    float acc[MT][NT][4];
#pragma unroll
    for (int i = 0; i < MT; i++)
#pragma unroll
        for (int j = 0; j < NT; j++)
#pragma unroll
            for (int e = 0; e < 4; e++) acc[i][j][e] = 0.0f;

    const int nch = K / BK;
#pragma unroll
    for (int s = 0; s < STG - 1; s++) {
        if (s < nch) load_stage();
        cpa_commit();
    }

    int slot_cmp = 0;
    for (int c = 0; c < nch; c++) {
        cpa_wait<STG - 2>();
        __syncthreads();
        const unsigned abp = a_base + (unsigned)(slot_cmp * ABUF) * 2u;
        const unsigned bbp = b_base + (unsigned)(slot_cmp * BBUF) * 2u;
        slot_cmp = (slot_cmp + 1 == STG) ? 0 : slot_cmp + 1;

#pragma unroll
        for (int ks = 0; ks < BK / 16; ks++) {
            unsigned afr[MT][4], bfr[NT][2];
#pragma unroll
            for (int i = 0; i < MT; i++)
                ldsm_x4(afr[i], abp + (unsigned)(i * 16 * ASTR + ks * 16) * 2u);
#pragma unroll
            for (int jj = 0; jj < NT / 2; jj++) {
                unsigned r4[4];
                ldsm_x4t(r4, bbp + (unsigned)(ks * 16 * BSTR + jj * 16) * 2u);
                bfr[2 * jj][0] = r4[0];
                bfr[2 * jj][1] = r4[1];
                bfr[2 * jj + 1][0] = r4[2];
                bfr[2 * jj + 1][1] = r4[3];
            }
#pragma unroll
            for (int i = 0; i < MT; i++)
#pragma unroll
                for (int j = 0; j < NT; j++) mma16(acc[i][j], afr[i], bfr[j]);
        }

        if (c + STG - 1 < nch) load_stage();
        cpa_commit();
    }

    // Epilogue
#pragma unroll
    for (int i = 0; i < MT; i++) {
        int r0 = m0 + wr * WM + i * 16 + g;
#pragma unroll
        for (int j = 0; j < NT; j++) {
            int col = n0 + wc * WN + j * 8 + tg * 2;
            float v0 = acc[i][j][0], v1 = acc[i][j][1];
            float v2 = acc[i][j][2], v3 = acc[i][j][3];
            if (RELU) {
                v0 = fmaxf(v0, 0.0f); v1 = fmaxf(v1, 0.0f);
                v2 = fmaxf(v2, 0.0f); v3 = fmaxf(v3, 0.0f);
            }
            if (OUTH) {
                __half* C = (__half*)Cv;
                *reinterpret_cast<__half2*>(&C[(long)r0 * ldc + col]) =
                    __floats2half2_rn(v0, v1);
                *reinterpret_cast<__half2*>(&C[(long)(r0 + 8) * ldc + col]) =
                    __floats2half2_rn(v2, v3);
            } else {
                float* C = (float*)Cv;
                float2 p01; p01.x = v0; p01.y = v1;
                float2 p23; p23.x = v2; p23.y = v3;
                *reinterpret_cast<float2*>(&C[(long)r0 * ldc + col]) = p01;
                *reinterpret_cast<float2*>(&C[(long)(r0 + 8) * ldc + col]) = p23;
            }
        }
    }
}

template <int BM, int BN, int STG, int BK, bool RELU, bool OUTH>
__global__ void __launch_bounds__(NTH, 2)
hgemm(const __half* __restrict__ A, int lda, long sAb, long sAh,
      const __half* __restrict__ Bg, int ldb, long sBb, long sBh,
      void* __restrict__ C, int ldc, long sCb, long sCh,
      int K, int hdiv) {
    const int z = blockIdx.z;
    const int zb = z / hdiv;
    const int zh = z % hdiv;
    char* Cp = (char*)C + ((long)zb * sCb + (long)zh * sCh) * (OUTH ? 2 : 4);
    hgemm_body<BM, BN, STG, BK, RELU, OUTH>(
        A + (long)zb * sAb + (long)zh * sAh, lda,
        Bg + (long)zb * sBb + (long)zh * sBh, ldb,
        Cp, ldc, K);
}

// Fused Q/K/V projection
__global__ void __launch_bounds__(NTH, 2)
qkv_h(const __half* __restrict__ xh,
      const __half* __restrict__ Wq, const __half* __restrict__ Wk,
      const __half* __restrict__ Wv,
      __half* __restrict__ q, __half* __restrict__ k, __half* __restrict__ v) {
    const int z = blockIdx.z;
    const __half* W = (z == 0) ? Wq : (z == 1) ? Wk : Wv;
    __half* C = (z == 0) ? q : (z == 1) ? k : v;
    hgemm_body<128, 128, 3, 32, false, true>(xh, D_, W, D_, C, D_, D_);
}

// ---------------------------------------------------------------------------
// Fused scores + mask + softmax (fp16 MMA). One CTA per (qtile64, b*h).
// smem (bytes): K half[512][72] at 0 (73728); Q half[64][72] at 73728;
// P fp32[64][516] overlays from 0 (132096); madd fp32[512] at 132096.
// ---------------------------------------------------------------------------
#define KSTR 72
#define QSTR 72
#define PSTR 516
#define AT_SMEM 134656

__global__ void __launch_bounds__(256, 1)
attn_h(const __half* __restrict__ q, const __half* __restrict__ k,
       const int* __restrict__ mask, float* __restrict__ attn,
       __half* __restrict__ ph) {
    extern __shared__ float sm[];
    __half* Ks = (__half*)sm;
    __half* Qs = (__half*)((char*)sm + 73728);
    float* P = sm;
    float* madd = (float*)((char*)sm + 132096);

    const int tid = threadIdx.x;
    const int lane = tid & 31;
    const int warp = tid >> 5;
    const int g = lane >> 2;
    const int tg = lane & 3;
    const int bh = blockIdx.y;
    const int b = bh >> 3;
    const int h = bh & 7;
    const int q0 = blockIdx.x * 64;

    const unsigned ks_u = (unsigned)__cvta_generic_to_shared(Ks);
    const unsigned qs_u = (unsigned)__cvta_generic_to_shared(Qs);

    {
        const int* mrow = mask + b * S_;
        madd[tid] = (mrow[tid] == 0) ? -1e9f : 0.0f;
        madd[tid + 256] = (mrow[tid + 256] == 0) ? -1e9f : 0.0f;
    }
    {
        const __half* qg = q + ((long)(b * S_ + q0)) * D_ + h * 64;
#pragma unroll
        for (int it = 0; it < 2; it++) {
            int f = tid + it * 256;
            int row = f >> 3, c8 = f & 7;
            cpa16(qs_u + (unsigned)(row * QSTR + c8 * 8) * 2u,
                  qg + (long)row * D_ + c8 * 8);
        }
        const __half* kg = k + ((long)(b * S_)) * D_ + h * 64;
#pragma unroll
        for (int it = 0; it < 16; it++) {
            int f = tid + it * 256;
            int row = f >> 3, c8 = f & 7;
            cpa16(ks_u + (unsigned)(row * KSTR + c8 * 8) * 2u,
                  kg + (long)row * D_ + c8 * 8);
        }
    }
    cpa_commit();
    cpa_wait<0>();
    __syncthreads();

    // Phase A: scores (warp w -> keys [64w,64w+64), all 64 queries)
    float acc[4][8][4];
#pragma unroll
    for (int i = 0; i < 4; i++)
#pragma unroll
        for (int j = 0; j < 8; j++)
#pragma unroll
            for (int e = 0; e < 4; e++) acc[i][j][e] = 0.0f;

    const unsigned a_base =
        qs_u + (unsigned)((((lane & 7) + 8 * ((lane >> 3) & 1)) * QSTR +
                           (lane >> 4) * 8) * 2);
    const unsigned b_base =
        ks_u + (unsigned)(((warp * 64 + (lane & 7) + 8 * (lane >> 4)) * KSTR +
                           8 * ((lane >> 3) & 1)) * 2);

#pragma unroll
    for (int ks = 0; ks < 4; ks++) {
        unsigned af[4][4], bf[8][2];
#pragma unroll
        for (int i = 0; i < 4; i++)
            ldsm_x4(af[i], a_base + (unsigned)(i * 16 * QSTR + ks * 16) * 2u);
#pragma unroll
        for (int jj = 0; jj < 4; jj++) {
            unsigned r4[4];
            ldsm_x4(r4, b_base + (unsigned)(jj * 16 * KSTR + ks * 16) * 2u);
            bf[2 * jj][0] = r4[0];
            bf[2 * jj][1] = r4[1];
            bf[2 * jj + 1][0] = r4[2];
            bf[2 * jj + 1][1] = r4[3];
        }
#pragma unroll
        for (int i = 0; i < 4; i++)
#pragma unroll
            for (int j = 0; j < 8; j++) mma16(acc[i][j], af[i], bf[j]);
    }
    __syncthreads();

    // Park raw scores into P (overwrites K/Q regions)
#pragma unroll
    for (int i = 0; i < 4; i++) {
        int r0 = 16 * i + g;
#pragma unroll
        for (int j = 0; j < 8; j++) {
            int c = warp * 64 + 8 * j + tg * 2;
            float2 lo; lo.x = acc[i][j][0]; lo.y = acc[i][j][1];
            float2 hi; hi.x = acc[i][j][2]; hi.y = acc[i][j][3];
            *reinterpret_cast<float2*>(&P[r0 * PSTR + c]) = lo;
            *reinterpret_cast<float2*>(&P[(r0 + 8) * PSTR + c]) = hi;
        }
    }
    __syncthreads();

    // Phase B: softmax (warp per row); fp32 probs -> attn, fp16 -> ph
#pragma unroll
    for (int rr = 0; rr < 8; rr++) {
        const int r = warp * 8 + rr;
        float* pr = P + r * PSTR;
        float4 vv[4];
        float mx = -3.4e38f;
#pragma unroll
        for (int c4 = 0; c4 < 4; c4++) {
            int col = c4 * 128 + lane * 4;
            float4 t = *reinterpret_cast<float4*>(&pr[col]);
            t.x = fmaf(t.x, 0.125f, madd[col]);
            t.y = fmaf(t.y, 0.125f, madd[col + 1]);
            t.z = fmaf(t.z, 0.125f, madd[col + 2]);
            t.w = fmaf(t.w, 0.125f, madd[col + 3]);
            vv[c4] = t;
            mx = fmaxf(mx, fmaxf(fmaxf(t.x, t.y), fmaxf(t.z, t.w)));
        }
#pragma unroll
        for (int o = 16; o; o >>= 1) mx = fmaxf(mx, __shfl_xor_sync(~0u, mx, o));
        float sum = 0.0f;
#pragma unroll
        for (int c4 = 0; c4 < 4; c4++) {
            vv[c4].x = __expf(vv[c4].x - mx);
            vv[c4].y = __expf(vv[c4].y - mx);
            vv[c4].z = __expf(vv[c4].z - mx);
            vv[c4].w = __expf(vv[c4].w - mx);
            sum += vv[c4].x + vv[c4].y + vv[c4].z + vv[c4].w;
        }
#pragma unroll
        for (int o = 16; o; o >>= 1) sum += __shfl_xor_sync(~0u, sum, o);
        const float inv = 1.0f / sum;
        const long rowbase = ((long)bh * S_ + q0 + r) * S_;
        float* ag = attn + rowbase;
        __half* pg = ph + rowbase;
#pragma unroll
        for (int c4 = 0; c4 < 4; c4++) {
            int col = c4 * 128 + lane * 4;
            float4 t = vv[c4];
            t.x *= inv; t.y *= inv; t.z *= inv; t.w *= inv;
            *reinterpret_cast<float4*>(&ag[col]) = t;
            *reinterpret_cast<__half2*>(&pg[col]) = __floats2half2_rn(t.x, t.y);
            *reinterpret_cast<__half2*>(&pg[col + 2]) = __floats2half2_rn(t.z, t.w);
        }
    }
}

// ---------------------------------------------------------------------------
// LayerNorm: in = p0 + p1 + residual; outputs fp32 x and fp16 xh.
// ---------------------------------------------------------------------------
__global__ void ln3_kernel(const float* __restrict__ p0,
                           const float* __restrict__ p1,
                           const float* __restrict__ res,
                           const float* __restrict__ g,
                           const float* __restrict__ bb,
                           float* __restrict__ out,
                           __half* __restrict__ outh) {
    const int row = blockIdx.x;
    const long base = (long)row * D_;
    const int t = threadIdx.x;

    float x0 = (p0[base + t] + p1[base + t]) + res[base + t];
    float x1 = (p0[base + t + 256] + p1[base + t + 256]) + res[base + t + 256];

    __shared__ float red[256];
    red[t] = x0 + x1;
    __syncthreads();
#pragma unroll
    for (int s = 128; s > 0; s >>= 1) {
        if (t < s) red[t] += red[t + s];
        __syncthreads();
    }
    const float mean = red[0] * (1.0f / D_);
    __syncthreads();

    float d0 = x0 - mean;
    float d1 = x1 - mean;
    red[t] = d0 * d0 + d1 * d1;
    __syncthreads();
#pragma unroll
    for (int s = 128; s > 0; s >>= 1) {
        if (t < s) red[t] += red[t + s];
        __syncthreads();
    }
    const float var = red[0] * (1.0f / D_);
    const float rs = rsqrtf(var + 1e-5f);

    float o0 = d0 * rs * g[t] + bb[t];
    float o1 = d1 * rs * g[t + 256] + bb[t + 256];
    out[base + t] = o0;
    out[base + t + 256] = o1;
    outh[base + t] = __float2half_rn(o0);
    outh[base + t + 256] = __float2half_rn(o1);
}

// ---------------------------------------------------------------------------
extern "C" void kernel_launch(void* const* d_in, const int* in_sizes, int n_in,
                              void* d_out, int out_size) {
    const float* enc = (const float*)d_in[0];
    const int* mask = (const int*)d_in[1];
    const float* Wq = (const float*)d_in[2];
    const float* Wk = (const float*)d_in[3];
    const float* Wv = (const float*)d_in[4];
    const float* Wo = (const float*)d_in[5];
    const float* ln1g = (const float*)d_in[6];
    const float* ln1b = (const float*)d_in[7];
    const float* W1 = (const float*)d_in[8];
    const float* W2 = (const float*)d_in[9];
    const float* ln2g = (const float*)d_in[10];
    const float* ln2b = (const float*)d_in[11];

    float *x, *tmp, *p2, *pos;
    __half *xh, *qh, *kh, *vh, *ch, *h1h, *ph, *wh;
    cudaGetSymbolAddress((void**)&x, g_x);
    cudaGetSymbolAddress((void**)&tmp, g_tmp);
    cudaGetSymbolAddress((void**)&p2, g_p2);
    cudaGetSymbolAddress((void**)&pos, g_pos);
    cudaGetSymbolAddress((void**)&xh, g_xh);
    cudaGetSymbolAddress((void**)&qh, g_qh);
    cudaGetSymbolAddress((void**)&kh, g_kh);
    cudaGetSymbolAddress((void**)&vh, g_vh);
    cudaGetSymbolAddress((void**)&ch, g_ch);
    cudaGetSymbolAddress((void**)&h1h, g_h1h);
    cudaGetSymbolAddress((void**)&ph, g_ph);
    cudaGetSymbolAddress((void**)&wh, g_wh);

    __half* Wq_h = wh;
    __half* Wk_h = Wq_h + 6 * WLD;
    __half* Wv_h = Wk_h + 6 * WLD;
    __half* Wo_h = Wv_h + 6 * WLD;
    __half* W1_h = Wo_h + 6 * WLD;
    __half* W2_h = W1_h + 6 * WF;

    float* out_x = (float*)d_out;
    float* out_attn = out_x + X_ELEMS;

    constexpr int SM_128 = HCfg<128, 128, 3, 32>::SMEM_BYTES;  // 56832
    constexpr int SM_64  = HCfg<128, 64, 3, 32>::SMEM_BYTES;   // 44544
    cudaFuncSetAttribute(hgemm<128, 128, 3, 32, false, false>,
                         cudaFuncAttributeMaxDynamicSharedMemorySize, SM_128);
    cudaFuncSetAttribute(hgemm<128, 128, 3, 32, false, true>,
                         cudaFuncAttributeMaxDynamicSharedMemorySize, SM_128);
    cudaFuncSetAttribute(hgemm<128, 128, 3, 32, true, true>,
                         cudaFuncAttributeMaxDynamicSharedMemorySize, SM_128);
    cudaFuncSetAttribute(hgemm<128, 64, 3, 32, false, true>,
                         cudaFuncAttributeMaxDynamicSharedMemorySize, SM_64);
    cudaFuncSetAttribute(qkv_h,
                         cudaFuncAttributeMaxDynamicSharedMemorySize, SM_128);
    cudaFuncSetAttribute(attn_h,
                         cudaFuncAttributeMaxDynamicSharedMemorySize, AT_SMEM);

    pos_kernel<<<(S_ * D_ + 255) / 256, 256>>>(pos);

    // Round all weights to fp16 once per launch
    round_h<<<(6 * WLD / 4 + 255) / 256, 256>>>(
        (const float4*)Wq, (__half2*)Wq_h, 6 * WLD / 4);
    round_h<<<(6 * WLD / 4 + 255) / 256, 256>>>(
        (const float4*)Wk, (__half2*)Wk_h, 6 * WLD / 4);
    round_h<<<(6 * WLD / 4 + 255) / 256, 256>>>(
        (const float4*)Wv, (__half2*)Wv_h, 6 * WLD / 4);
    round_h<<<(6 * WLD / 4 + 255) / 256, 256>>>(
        (const float4*)Wo, (__half2*)Wo_h, 6 * WLD / 4);
    round_h<<<(6 * WF / 4 + 255) / 256, 256>>>(
        (const float4*)W1, (__half2*)W1_h, 6 * WF / 4);
    round_h<<<(6 * WF / 4 + 255) / 256, 256>>>(
        (const float4*)W2, (__half2*)W2_h, 6 * WF / 4);

    add_pos_kernel<<<(X_ELEMS + 255) / 256, 256>>>(x, xh, enc, pos);

    for (int l = 0; l < L_; l++) {
        float* attn_l = out_attn + (long)l * ATTN_PER_LAYER;

        // Q,K,V projections (fp16 out)
        qkv_h<<<dim3(4, 32, 3), NTH, SM_128>>>(
            xh, Wq_h + l * WLD, Wk_h + l * WLD, Wv_h + l * WLD, qh, kh, vh);

        // Fused scores + mask + softmax -> exact fp32 probs + fp16 probs
        attn_h<<<dim3(8, 64), 256, AT_SMEM>>>(qh, kh, mask, attn_l, ph);

        // ctx = P(h16) @ V(h16) per (b,h) -> ctx fp16 [B,S,H*DV]
        hgemm<128, 64, 3, 32, false, true><<<dim3(1, 4, B_ * H_), NTH, SM_64>>>(
            ph, S_, (long)H_ * S_ * S_, (long)S_ * S_,
            vh, D_, (long)S_ * D_, DV_,
            ch, D_, (long)S_ * D_, DV_,
            S_, H_);

        // Wo projection split-K=2 -> fp32 partials tmp/p2; reduce in LN1
        hgemm<128, 128, 3, 32, false, false><<<dim3(4, 32, 2), NTH, SM_128>>>(
            ch, D_, 0, 256,
            Wo_h + l * WLD, D_, 0, (long)256 * D_,
            tmp, D_, 0, (long)(p2 - tmp),
            256, 2);
        ln3_kernel<<<M_, 256>>>(tmp, p2, x, ln1g + l * D_, ln1b + l * D_, x, xh);

        // FFN: relu(xh @ W1) -> h1 (fp16)
        hgemm<128, 128, 3, 32, true, true><<<dim3(16, 32, 1), NTH, SM_128>>>(
            xh, D_, 0, 0, W1_h + l * WF, DFF_, 0, 0, h1h, DFF_, 0, 0,
            D_, 1);
        // W2 split-K=2 -> fp32 partials; reduce in LN2
        hgemm<128, 128, 3, 32, false, false><<<dim3(4, 32, 2), NTH, SM_128>>>(
            h1h, DFF_, 0, 1024,
            W2_h + l * WF, D_, 0, (long)1024 * D_,
            tmp, D_, 0, (long)(p2 - tmp),
            1024, 2);
        ln3_kernel<<<M_, 256>>>(tmp, p2, x, ln2g + l * D_, ln2b + l * D_, x, xh);
    }

    cudaMemcpyAsync(out_x, x, (size_t)X_ELEMS * sizeof(float),
                    cudaMemcpyDeviceToDevice, 0);
}

// round 17
// speedup vs baseline: 1.4614x; 1.0295x over previous
#include <cuda_runtime.h>
#include <cuda_fp16.h>
#include <math.h>

// Problem constants
#define B_ 8
#define S_ 512
#define D_ 512
#define H_ 8
#define DK_ 64
#define DV_ 64
#define DFF_ 2048
#define L_ 6
#define M_ (B_ * S_)               // 4096 rows
#define X_ELEMS (M_ * D_)          // 2,097,152
#define ATTN_PER_LAYER ((long)B_ * H_ * S_ * S_)  // 16,777,216
#define WLD (D_ * D_)              // 262144
#define WF (D_ * DFF_)             // 1048576

// Device scratch (allocations forbidden; __device__ globals)
__device__ float  g_x[X_ELEMS];          // residual stream (fp32)
__device__ float  g_tmp[X_ELEMS];        // split-K partial 0 (fp32)
__device__ float  g_p2[X_ELEMS];         // split-K partial 1 (fp32)
__device__ float  g_pos[S_ * D_];
__device__ __half g_xh[X_ELEMS];         // fp16 copy of x (GEMM A input)
__device__ __half g_qh[X_ELEMS];
__device__ __half g_kh[X_ELEMS];
__device__ __half g_vh[X_ELEMS];
__device__ __half g_ch[X_ELEMS];         // ctx fp16
__device__ __half g_h1h[M_ * DFF_];      // FFN hidden fp16
__device__ __half g_ph[ATTN_PER_LAYER];  // attn probs fp16 (for P@V)
__device__ __half g_wh[6 * (4 * WLD + 2 * WF)];  // fp16 weights

// ---------------------------------------------------------------------------
// helpers
// ---------------------------------------------------------------------------
__device__ __forceinline__ void mma16(float* d, const unsigned* a, const unsigned* b) {
    asm volatile(
        "mma.sync.aligned.m16n8k16.row.col.f32.f16.f16.f32 "
        "{%0,%1,%2,%3}, {%4,%5,%6,%7}, {%8,%9}, {%0,%1,%2,%3};"
        : "+f"(d[0]), "+f"(d[1]), "+f"(d[2]), "+f"(d[3])
        : "r"(a[0]), "r"(a[1]), "r"(a[2]), "r"(a[3]), "r"(b[0]), "r"(b[1]));
}
__device__ __forceinline__ void ldsm_x4(unsigned* r, unsigned addr) {
    asm volatile("ldmatrix.sync.aligned.m8n8.x4.shared.b16 {%0,%1,%2,%3}, [%4];"
                 : "=r"(r[0]), "=r"(r[1]), "=r"(r[2]), "=r"(r[3]) : "r"(addr));
}
__device__ __forceinline__ void ldsm_x4t(unsigned* r, unsigned addr) {
    asm volatile("ldmatrix.sync.aligned.m8n8.x4.trans.shared.b16 {%0,%1,%2,%3}, [%4];"
                 : "=r"(r[0]), "=r"(r[1]), "=r"(r[2]), "=r"(r[3]) : "r"(addr));
}
__device__ __forceinline__ void cpa16(unsigned dst, const void* src) {
    asm volatile("cp.async.cg.shared.global [%0], [%1], 16;" :: "r"(dst), "l"(src));
}
__device__ __forceinline__ void cpa_commit() {
    asm volatile("cp.async.commit_group;" ::: "memory");
}
template <int N>
__device__ __forceinline__ void cpa_wait() {
    asm volatile("cp.async.wait_group %0;" :: "n"(N) : "memory");
}

// ---------------------------------------------------------------------------
// fp32 -> fp16 rounding copy (weights)
// ---------------------------------------------------------------------------
__global__ void round_h(const float4* __restrict__ in,
                        __half2* __restrict__ out, int n4) {
    int i = blockIdx.x * blockDim.x + threadIdx.x;
    if (i >= n4) return;
    float4 v = in[i];
    out[2 * i] = __floats2half2_rn(v.x, v.y);
    out[2 * i + 1] = __floats2half2_rn(v.z, v.w);
}

// ---------------------------------------------------------------------------
// Positional table (double precision, matches numpy float64 path)
// ---------------------------------------------------------------------------
__global__ void pos_kernel(float* __restrict__ pos) {
    int idx = blockIdx.x * blockDim.x + threadIdx.x;
    if (idx >= S_ * D_) return;
    int s = idx >> 9;
    int d = idx & 511;
    double val = 0.0;
    if (s > 0) {
        double ang = (double)s * exp(-log(10000.0) * (2.0 * (double)d / (double)D_));
        val = (d & 1) ? cos(ang) : sin(ang);
    }
    pos[idx] = (float)val;
}

__global__ void add_pos_kernel(float* __restrict__ x, __half* __restrict__ xh,
                               const float* __restrict__ enc,
                               const float* __restrict__ pos) {
    int idx = blockIdx.x * blockDim.x + threadIdx.x;
    if (idx >= X_ELEMS) return;
    int sd = idx & (S_ * D_ - 1);
    float v = enc[idx] + pos[sd];
    x[idx] = v;
    xh[idx] = __float2half_rn(v);
}

// ---------------------------------------------------------------------------
// fp16 tensor-core GEMM (m16n8k16), BK-wide cp.async pipeline (BK=64, 3 st),
// 128 threads, 2x2 warp grid, 64x(BN/2) warp tiles.
//   C[m,n] = sum_k A[m,k] * B[k,n]   (A fp16 [m][k]; B fp16 k-major [k][n])
// A frags: ldmatrix.x4; B frags: ldmatrix.x4.trans. fp32 accumulation.
// RELU: relu epilogue. OUTH: fp16 output (else fp32, for split-K partials).
// ---------------------------------------------------------------------------
#define NTH 128

template <int BM, int BN, int STG, int BK>
struct HCfg {
    static constexpr int ASTR = BK + 8;             // halves
    static constexpr int ABUF = BM * ASTR;
    static constexpr int BSTR = BN + 8;
    static constexpr int BBUF = BK * BSTR;
    static constexpr int SMEM_BYTES = STG * (ABUF + BBUF) * 2;
};

template <int BM, int BN, int STG, int BK, bool RELU, bool OUTH>
__device__ __forceinline__ void hgemm_body(
    const __half* __restrict__ A, int lda,
    const __half* __restrict__ Bg, int ldb,
    void* __restrict__ Cv, int ldc, int K) {
    using CF = HCfg<BM, BN, STG, BK>;
    constexpr int ASTR = CF::ASTR, ABUF = CF::ABUF;
    constexpr int BSTR = CF::BSTR, BBUF = CF::BBUF;
    constexpr int KF8 = BK / 8;                     // 16B chunks per A row
    constexpr int AROW = NTH / KF8;                 // A rows per iter
    constexpr int AF = BM / AROW;
    constexpr int BROW = NTH / (BN / 8);            // B rows per iter
    constexpr int BF = BK / BROW;
    constexpr int WM = BM / 2, WN = BN / 2;
    constexpr int MT = WM / 16, NT = WN / 8;

    extern __shared__ __half hs[];
    __half* As = hs;
    __half* Bs = hs + STG * ABUF;
    const unsigned as_u = (unsigned)__cvta_generic_to_shared(As);
    const unsigned bs_u = (unsigned)__cvta_generic_to_shared(Bs);

    const int tid = threadIdx.x;
    const int lane = tid & 31;
    const int warp = tid >> 5;
    const int g = lane >> 2;
    const int tg = lane & 3;
    const int wr = warp & 1;
    const int wc = warp >> 1;
    const int m0 = blockIdx.y * BM;
    const int n0 = blockIdx.x * BN;

    const int ra = tid / KF8, ca = tid % KF8;
    const __half* pA = A + (long)(m0 + ra) * lda + ca * 8;
    const unsigned aoff0 = as_u + (unsigned)(ra * ASTR + ca * 8) * 2u;
    const int rb = tid / (BN / 8), cb = tid % (BN / 8);
    const __half* pB = Bg + (long)rb * ldb + n0 + cb * 8;
    const unsigned boff0 = bs_u + (unsigned)(rb * BSTR + cb * 8) * 2u;

    int slot_ld = 0;
    auto load_stage = [&]() {
        const unsigned ao = (unsigned)(slot_ld * ABUF) * 2u;
        const unsigned bo = (unsigned)(slot_ld * BBUF) * 2u;
#pragma unroll
        for (int it = 0; it < AF; it++)
            cpa16(aoff0 + ao + (unsigned)(it * AROW * ASTR) * 2u,
                  pA + (long)it * AROW * lda);
        pA += BK;
#pragma unroll
        for (int it = 0; it < BF; it++)
            cpa16(boff0 + bo + (unsigned)(it * BROW * BSTR) * 2u,
                  pB + (long)it * BROW * ldb);
        pB += (long)BK * ldb;
        slot_ld = (slot_ld + 1 == STG) ? 0 : slot_ld + 1;
    };

    const unsigned a_base =
        as_u + (unsigned)(((wr * WM + (lane & 7) + 8 * ((lane >> 3) & 1)) * ASTR +
                           (lane >> 4) * 8) * 2);
    const unsigned b_base =
        bs_u + (unsigned)((((lane & 7) + 8 * ((lane >> 3) & 1)) * BSTR +
                           wc * WN + (lane >> 4) * 8) * 2);

    float acc[MT][NT][4];
#pragma unroll
    for (int i = 0; i < MT; i++)
#pragma unroll
        for (int j = 0; j < NT; j++)
#pragma unroll
            for (int e = 0; e < 4; e++) acc[i][j][e] = 0.0f;

    const int nch = K / BK;
#pragma unroll
    for (int s = 0; s < STG - 1; s++) {
        if (s < nch) load_stage();
        cpa_commit();
    }

    int slot_cmp = 0;
    for (int c = 0; c < nch; c++) {
        cpa_wait<STG - 2>();
        __syncthreads();
        const unsigned abp = a_base + (unsigned)(slot_cmp * ABUF) * 2u;
        const unsigned bbp = b_base + (unsigned)(slot_cmp * BBUF) * 2u;
        slot_cmp = (slot_cmp + 1 == STG) ? 0 : slot_cmp + 1;

#pragma unroll
        for (int ks = 0; ks < BK / 16; ks++) {
            unsigned afr[MT][4], bfr[NT][2];
#pragma unroll
            for (int i = 0; i < MT; i++)
                ldsm_x4(afr[i], abp + (unsigned)(i * 16 * ASTR + ks * 16) * 2u);
#pragma unroll
            for (int jj = 0; jj < NT / 2; jj++) {
                unsigned r4[4];
                ldsm_x4t(r4, bbp + (unsigned)(ks * 16 * BSTR + jj * 16) * 2u);
                bfr[2 * jj][0] = r4[0];
                bfr[2 * jj][1] = r4[1];
                bfr[2 * jj + 1][0] = r4[2];
                bfr[2 * jj + 1][1] = r4[3];
            }
#pragma unroll
            for (int i = 0; i < MT; i++)
#pragma unroll
                for (int j = 0; j < NT; j++) mma16(acc[i][j], afr[i], bfr[j]);
        }

        if (c + STG - 1 < nch) load_stage();
        cpa_commit();
    }

    // Epilogue
#pragma unroll
    for (int i = 0; i < MT; i++) {
        int r0 = m0 + wr * WM + i * 16 + g;
#pragma unroll
        for (int j = 0; j < NT; j++) {
            int col = n0 + wc * WN + j * 8 + tg * 2;
            float v0 = acc[i][j][0], v1 = acc[i][j][1];
            float v2 = acc[i][j][2], v3 = acc[i][j][3];
            if (RELU) {
                v0 = fmaxf(v0, 0.0f); v1 = fmaxf(v1, 0.0f);
                v2 = fmaxf(v2, 0.0f); v3 = fmaxf(v3, 0.0f);
            }
            if (OUTH) {
                __half* C = (__half*)Cv;
                *reinterpret_cast<__half2*>(&C[(long)r0 * ldc + col]) =
                    __floats2half2_rn(v0, v1);
                *reinterpret_cast<__half2*>(&C[(long)(r0 + 8) * ldc + col]) =
                    __floats2half2_rn(v2, v3);
            } else {
                float* C = (float*)Cv;
                float2 p01; p01.x = v0; p01.y = v1;
                float2 p23; p23.x = v2; p23.y = v3;
                *reinterpret_cast<float2*>(&C[(long)r0 * ldc + col]) = p01;
                *reinterpret_cast<float2*>(&C[(long)(r0 + 8) * ldc + col]) = p23;
            }
        }
    }
}

template <int BM, int BN, int STG, int BK, bool RELU, bool OUTH>
__global__ void __launch_bounds__(NTH, 2)
hgemm(const __half* __restrict__ A, int lda, long sAb, long sAh,
      const __half* __restrict__ Bg, int ldb, long sBb, long sBh,
      void* __restrict__ C, int ldc, long sCb, long sCh,
      int K, int hdiv) {
    const int z = blockIdx.z;
    const int zb = z / hdiv;
    const int zh = z % hdiv;
    char* Cp = (char*)C + ((long)zb * sCb + (long)zh * sCh) * (OUTH ? 2 : 4);
    hgemm_body<BM, BN, STG, BK, RELU, OUTH>(
        A + (long)zb * sAb + (long)zh * sAh, lda,
        Bg + (long)zb * sBb + (long)zh * sBh, ldb,
        Cp, ldc, K);
}

// Fused Q/K/V projection
__global__ void __launch_bounds__(NTH, 2)
qkv_h(const __half* __restrict__ xh,
      const __half* __restrict__ Wq, const __half* __restrict__ Wk,
      const __half* __restrict__ Wv,
      __half* __restrict__ q, __half* __restrict__ k, __half* __restrict__ v) {
    const int z = blockIdx.z;
    const __half* W = (z == 0) ? Wq : (z == 1) ? Wk : Wv;
    __half* C = (z == 0) ? q : (z == 1) ? k : v;
    hgemm_body<128, 128, 3, 64, false, true>(xh, D_, W, D_, C, D_, D_);
}

// ---------------------------------------------------------------------------
// Fused scores + mask + softmax (fp16 MMA). One CTA per (qtile64, b*h).
// smem (bytes): K half[512][72] at 0 (73728); Q half[64][72] at 73728;
// P fp32[64][516] overlays from 0 (132096); madd fp32[512] at 132096.
// ---------------------------------------------------------------------------
#define KSTR 72
#define QSTR 72
#define PSTR 516
#define AT_SMEM 134656

__global__ void __launch_bounds__(256, 1)
attn_h(const __half* __restrict__ q, const __half* __restrict__ k,
       const int* __restrict__ mask, float* __restrict__ attn,
       __half* __restrict__ ph) {
    extern __shared__ float sm[];
    __half* Ks = (__half*)sm;
    __half* Qs = (__half*)((char*)sm + 73728);
    float* P = sm;
    float* madd = (float*)((char*)sm + 132096);

    const int tid = threadIdx.x;
    const int lane = tid & 31;
    const int warp = tid >> 5;
    const int g = lane >> 2;
    const int tg = lane & 3;
    const int bh = blockIdx.y;
    const int b = bh >> 3;
    const int h = bh & 7;
    const int q0 = blockIdx.x * 64;

    const unsigned ks_u = (unsigned)__cvta_generic_to_shared(Ks);
    const unsigned qs_u = (unsigned)__cvta_generic_to_shared(Qs);

    {
        const int* mrow = mask + b * S_;
        madd[tid] = (mrow[tid] == 0) ? -1e9f : 0.0f;
        madd[tid + 256] = (mrow[tid + 256] == 0) ? -1e9f : 0.0f;
    }
    {
        const __half* qg = q + ((long)(b * S_ + q0)) * D_ + h * 64;
#pragma unroll
        for (int it = 0; it < 2; it++) {
            int f = tid + it * 256;
            int row = f >> 3, c8 = f & 7;
            cpa16(qs_u + (unsigned)(row * QSTR + c8 * 8) * 2u,
                  qg + (long)row * D_ + c8 * 8);
        }
        const __half* kg = k + ((long)(b * S_)) * D_ + h * 64;
#pragma unroll
        for (int it = 0; it < 16; it++) {
            int f = tid + it * 256;
            int row = f >> 3, c8 = f & 7;
            cpa16(ks_u + (unsigned)(row * KSTR + c8 * 8) * 2u,
                  kg + (long)row * D_ + c8 * 8);
        }
    }
    cpa_commit();
    cpa_wait<0>();
    __syncthreads();

    // Phase A: scores (warp w -> keys [64w,64w+64), all 64 queries)
    float acc[4][8][4];
#pragma unroll
    for (int i = 0; i < 4; i++)
#pragma unroll
        for (int j = 0; j < 8; j++)
#pragma unroll
            for (int e = 0; e < 4; e++) acc[i][j][e] = 0.0f;

    const unsigned a_base =
        qs_u + (unsigned)((((lane & 7) + 8 * ((lane >> 3) & 1)) * QSTR +
                           (lane >> 4) * 8) * 2);
    const unsigned b_base =
        ks_u + (unsigned)(((warp * 64 + (lane & 7) + 8 * (lane >> 4)) * KSTR +
                           8 * ((lane >> 3) & 1)) * 2);

#pragma unroll
    for (int ks = 0; ks < 4; ks++) {
        unsigned af[4][4], bf[8][2];
#pragma unroll
        for (int i = 0; i < 4; i++)
            ldsm_x4(af[i], a_base + (unsigned)(i * 16 * QSTR + ks * 16) * 2u);
#pragma unroll
        for (int jj = 0; jj < 4; jj++) {
            unsigned r4[4];
            ldsm_x4(r4, b_base + (unsigned)(jj * 16 * KSTR + ks * 16) * 2u);
            bf[2 * jj][0] = r4[0];
            bf[2 * jj][1] = r4[1];
            bf[2 * jj + 1][0] = r4[2];
            bf[2 * jj + 1][1] = r4[3];
        }
#pragma unroll
        for (int i = 0; i < 4; i++)
#pragma unroll
            for (int j = 0; j < 8; j++) mma16(acc[i][j], af[i], bf[j]);
    }
    __syncthreads();

    // Park raw scores into P (overwrites K/Q regions)
#pragma unroll
    for (int i = 0; i < 4; i++) {
        int r0 = 16 * i + g;
#pragma unroll
        for (int j = 0; j < 8; j++) {
            int c = warp * 64 + 8 * j + tg * 2;
            float2 lo; lo.x = acc[i][j][0]; lo.y = acc[i][j][1];
            float2 hi; hi.x = acc[i][j][2]; hi.y = acc[i][j][3];
            *reinterpret_cast<float2*>(&P[r0 * PSTR + c]) = lo;
            *reinterpret_cast<float2*>(&P[(r0 + 8) * PSTR + c]) = hi;
        }
    }
    __syncthreads();

    // Phase B: softmax (warp per row); fp32 probs -> attn, fp16 -> ph
#pragma unroll
    for (int rr = 0; rr < 8; rr++) {
        const int r = warp * 8 + rr;
        float* pr = P + r * PSTR;
        float4 vv[4];
        float mx = -3.4e38f;
#pragma unroll
        for (int c4 = 0; c4 < 4; c4++) {
            int col = c4 * 128 + lane * 4;
            float4 t = *reinterpret_cast<float4*>(&pr[col]);
            t.x = fmaf(t.x, 0.125f, madd[col]);
            t.y = fmaf(t.y, 0.125f, madd[col + 1]);
            t.z = fmaf(t.z, 0.125f, madd[col + 2]);
            t.w = fmaf(t.w, 0.125f, madd[col + 3]);
            vv[c4] = t;
            mx = fmaxf(mx, fmaxf(fmaxf(t.x, t.y), fmaxf(t.z, t.w)));
        }
#pragma unroll
        for (int o = 16; o; o >>= 1) mx = fmaxf(mx, __shfl_xor_sync(~0u, mx, o));
        float sum = 0.0f;
#pragma unroll
        for (int c4 = 0; c4 < 4; c4++) {
            vv[c4].x = __expf(vv[c4].x - mx);
            vv[c4].y = __expf(vv[c4].y - mx);
            vv[c4].z = __expf(vv[c4].z - mx);
            vv[c4].w = __expf(vv[c4].w - mx);
            sum += vv[c4].x + vv[c4].y + vv[c4].z + vv[c4].w;
        }
#pragma unroll
        for (int o = 16; o; o >>= 1) sum += __shfl_xor_sync(~0u, sum, o);
        const float inv = 1.0f / sum;
        const long rowbase = ((long)bh * S_ + q0 + r) * S_;
        float* ag = attn + rowbase;
        __half* pg = ph + rowbase;
#pragma unroll
        for (int c4 = 0; c4 < 4; c4++) {
            int col = c4 * 128 + lane * 4;
            float4 t = vv[c4];
            t.x *= inv; t.y *= inv; t.z *= inv; t.w *= inv;
            *reinterpret_cast<float4*>(&ag[col]) = t;
            *reinterpret_cast<__half2*>(&pg[col]) = __floats2half2_rn(t.x, t.y);
            *reinterpret_cast<__half2*>(&pg[col + 2]) = __floats2half2_rn(t.z, t.w);
        }
    }
}

// ---------------------------------------------------------------------------
// LayerNorm: in = p0 + p1 + residual; outputs fp32 x and fp16 xh.
// ---------------------------------------------------------------------------
__global__ void ln3_kernel(const float* __restrict__ p0,
                           const float* __restrict__ p1,
                           const float* __restrict__ res,
                           const float* __restrict__ g,
                           const float* __restrict__ bb,
                           float* __restrict__ out,
                           __half* __restrict__ outh) {
    const int row = blockIdx.x;
    const long base = (long)row * D_;
    const int t = threadIdx.x;

    float x0 = (p0[base + t] + p1[base + t]) + res[base + t];
    float x1 = (p0[base + t + 256] + p1[base + t + 256]) + res[base + t + 256];

    __shared__ float red[256];
    red[t] = x0 + x1;
    __syncthreads();
#pragma unroll
    for (int s = 128; s > 0; s >>= 1) {
        if (t < s) red[t] += red[t + s];
        __syncthreads();
    }
    const float mean = red[0] * (1.0f / D_);
    __syncthreads();

    float d0 = x0 - mean;
    float d1 = x1 - mean;
    red[t] = d0 * d0 + d1 * d1;
    __syncthreads();
#pragma unroll
    for (int s = 128; s > 0; s >>= 1) {
        if (t < s) red[t] += red[t + s];
        __syncthreads();
    }
    const float var = red[0] * (1.0f / D_);
    const float rs = rsqrtf(var + 1e-5f);

    float o0 = d0 * rs * g[t] + bb[t];
    float o1 = d1 * rs * g[t + 256] + bb[t + 256];
    out[base + t] = o0;
    out[base + t + 256] = o1;
    outh[base + t] = __float2half_rn(o0);
    outh[base + t + 256] = __float2half_rn(o1);
}

// ---------------------------------------------------------------------------
extern "C" void kernel_launch(void* const* d_in, const int* in_sizes, int n_in,
                              void* d_out, int out_size) {
    const float* enc = (const float*)d_in[0];
    const int* mask = (const int*)d_in[1];
    const float* Wq = (const float*)d_in[2];
    const float* Wk = (const float*)d_in[3];
    const float* Wv = (const float*)d_in[4];
    const float* Wo = (const float*)d_in[5];
    const float* ln1g = (const float*)d_in[6];
    const float* ln1b = (const float*)d_in[7];
    const float* W1 = (const float*)d_in[8];
    const float* W2 = (const float*)d_in[9];
    const float* ln2g = (const float*)d_in[10];
    const float* ln2b = (const float*)d_in[11];

    float *x, *tmp, *p2, *pos;
    __half *xh, *qh, *kh, *vh, *ch, *h1h, *ph, *wh;
    cudaGetSymbolAddress((void**)&x, g_x);
    cudaGetSymbolAddress((void**)&tmp, g_tmp);
    cudaGetSymbolAddress((void**)&p2, g_p2);
    cudaGetSymbolAddress((void**)&pos, g_pos);
    cudaGetSymbolAddress((void**)&xh, g_xh);
    cudaGetSymbolAddress((void**)&qh, g_qh);
    cudaGetSymbolAddress((void**)&kh, g_kh);
    cudaGetSymbolAddress((void**)&vh, g_vh);
    cudaGetSymbolAddress((void**)&ch, g_ch);
    cudaGetSymbolAddress((void**)&h1h, g_h1h);
    cudaGetSymbolAddress((void**)&ph, g_ph);
    cudaGetSymbolAddress((void**)&wh, g_wh);

    __half* Wq_h = wh;
    __half* Wk_h = Wq_h + 6 * WLD;
    __half* Wv_h = Wk_h + 6 * WLD;
    __half* Wo_h = Wv_h + 6 * WLD;
    __half* W1_h = Wo_h + 6 * WLD;
    __half* W2_h = W1_h + 6 * WF;

    float* out_x = (float*)d_out;
    float* out_attn = out_x + X_ELEMS;

    constexpr int SM_128 = HCfg<128, 128, 3, 64>::SMEM_BYTES;  // 107520
    constexpr int SM_64  = HCfg<128, 64, 3, 64>::SMEM_BYTES;   // 82944
    cudaFuncSetAttribute(hgemm<128, 128, 3, 64, false, false>,
                         cudaFuncAttributeMaxDynamicSharedMemorySize, SM_128);
    cudaFuncSetAttribute(hgemm<128, 128, 3, 64, false, true>,
                         cudaFuncAttributeMaxDynamicSharedMemorySize, SM_128);
    cudaFuncSetAttribute(hgemm<128, 128, 3, 64, true, true>,
                         cudaFuncAttributeMaxDynamicSharedMemorySize, SM_128);
    cudaFuncSetAttribute(hgemm<128, 64, 3, 64, false, true>,
                         cudaFuncAttributeMaxDynamicSharedMemorySize, SM_64);
    cudaFuncSetAttribute(qkv_h,
                         cudaFuncAttributeMaxDynamicSharedMemorySize, SM_128);
    cudaFuncSetAttribute(attn_h,
                         cudaFuncAttributeMaxDynamicSharedMemorySize, AT_SMEM);

    pos_kernel<<<(S_ * D_ + 255) / 256, 256>>>(pos);

    // Round all weights to fp16 once per launch
    round_h<<<(6 * WLD / 4 + 255) / 256, 256>>>(
        (const float4*)Wq, (__half2*)Wq_h, 6 * WLD / 4);
    round_h<<<(6 * WLD / 4 + 255) / 256, 256>>>(
        (const float4*)Wk, (__half2*)Wk_h, 6 * WLD / 4);
    round_h<<<(6 * WLD / 4 + 255) / 256, 256>>>(
        (const float4*)Wv, (__half2*)Wv_h, 6 * WLD / 4);
    round_h<<<(6 * WLD / 4 + 255) / 256, 256>>>(
        (const float4*)Wo, (__half2*)Wo_h, 6 * WLD / 4);
    round_h<<<(6 * WF / 4 + 255) / 256, 256>>>(
        (const float4*)W1, (__half2*)W1_h, 6 * WF / 4);
    round_h<<<(6 * WF / 4 + 255) / 256, 256>>>(
        (const float4*)W2, (__half2*)W2_h, 6 * WF / 4);

    add_pos_kernel<<<(X_ELEMS + 255) / 256, 256>>>(x, xh, enc, pos);

    for (int l = 0; l < L_; l++) {
        float* attn_l = out_attn + (long)l * ATTN_PER_LAYER;

        // Q,K,V projections (fp16 out)
        qkv_h<<<dim3(4, 32, 3), NTH, SM_128>>>(
            xh, Wq_h + l * WLD, Wk_h + l * WLD, Wv_h + l * WLD, qh, kh, vh);

        // Fused scores + mask + softmax -> exact fp32 probs + fp16 probs
        attn_h<<<dim3(8, 64), 256, AT_SMEM>>>(qh, kh, mask, attn_l, ph);

        // ctx = P(h16) @ V(h16) per (b,h) -> ctx fp16 [B,S,H*DV]
        hgemm<128, 64, 3, 64, false, true><<<dim3(1, 4, B_ * H_), NTH, SM_64>>>(
            ph, S_, (long)H_ * S_ * S_, (long)S_ * S_,
            vh, D_, (long)S_ * D_, DV_,
            ch, D_, (long)S_ * D_, DV_,
            S_, H_);

        // Wo projection split-K=2 -> fp32 partials tmp/p2; reduce in LN1
        hgemm<128, 128, 3, 64, false, false><<<dim3(4, 32, 2), NTH, SM_128>>>(
            ch, D_, 0, 256,
            Wo_h + l * WLD, D_, 0, (long)256 * D_,
            tmp, D_, 0, (long)(p2 - tmp),
            256, 2);
        ln3_kernel<<<M_, 256>>>(tmp, p2, x, ln1g + l * D_, ln1b + l * D_, x, xh);

        // FFN: relu(xh @ W1) -> h1 (fp16)
        hgemm<128, 128, 3, 64, true, true><<<dim3(16, 32, 1), NTH, SM_128>>>(
            xh, D_, 0, 0, W1_h + l * WF, DFF_, 0, 0, h1h, DFF_, 0, 0,
            D_, 1);
        // W2 split-K=2 -> fp32 partials; reduce in LN2
        hgemm<128, 128, 3, 64, false, false><<<dim3(4, 32, 2), NTH, SM_128>>>(
            h1h, DFF_, 0, 1024,
            W2_h + l * WF, D_, 0, (long)1024 * D_,
            tmp, D_, 0, (long)(p2 - tmp),
            1024, 2);
        ln3_kernel<<<M_, 256>>>(tmp, p2, x, ln2g + l * D_, ln2b + l * D_, x, xh);
    }

    cudaMemcpyAsync(out_x, x, (size_t)X_ELEMS * sizeof(float),
                    cudaMemcpyDeviceToDevice, 0);
}